// round 2
// baseline (speedup 1.0000x reference)
#include <cuda_runtime.h>

// PSRoIAlign: feat [B=4, C=784, H=80, W=80] f32, rois [N=512, 5] f32
// out [N, 16, 7, 7] f32. Channel for output element (co,ph,pw) is r = co*49+ph*7+pw.
// SR=2 sampling, bilinear, mask outside [-1, H]/[-1, W], mean over 4 samples.

#define PH 7
#define PW 7
#define HH 80
#define WW 80
#define CC 784
#define SR 2

__global__ void psroi_align_kernel(const float* __restrict__ feat,
                                   const float* __restrict__ rois,
                                   float* __restrict__ out,
                                   int total)  // total = N * 784
{
    int tid = blockIdx.x * blockDim.x + threadIdx.x;
    if (tid >= total) return;

    int n = tid / (PH * PW * 16);         // roi index
    int r = tid - n * (PH * PW * 16);     // = channel index = co*49 + ph*7 + pw
    int pw = r % PW;
    int ph = (r / PW) % PH;

    // roi params (5 floats, broadcast within the many threads of the same roi)
    const float* roi = rois + n * 5;
    int   b  = (int)roi[0];
    float x1 = roi[1] * (float)WW;
    float y1 = roi[2] * (float)HH;
    float x2 = roi[3] * (float)WW;
    float y2 = roi[4] * (float)HH;

    float roi_h = fmaxf(y2 - y1, 0.1f);
    float roi_w = fmaxf(x2 - x1, 0.1f);
    float bin_h = roi_h * (1.0f / PH);
    float bin_w = roi_w * (1.0f / PW);

    const float* f = feat + ((size_t)b * CC + (size_t)r) * (HH * WW);

    float acc = 0.0f;

    #pragma unroll
    for (int sy = 0; sy < SR; ++sy) {
        float ys = y1 + (float)ph * bin_h + ((float)sy + 0.5f) * bin_h * (1.0f / SR);
        bool ymask = (ys >= -1.0f) && (ys <= (float)HH);
        float yc = fminf(fmaxf(ys, 0.0f), (float)(HH - 1));
        int y0 = (int)floorf(yc);
        int y1i = min(y0 + 1, HH - 1);
        float ly = yc - (float)y0;
        float hy = 1.0f - ly;

        #pragma unroll
        for (int sx = 0; sx < SR; ++sx) {
            float xs = x1 + (float)pw * bin_w + ((float)sx + 0.5f) * bin_w * (1.0f / SR);
            bool xmask = (xs >= -1.0f) && (xs <= (float)WW);
            float xc = fminf(fmaxf(xs, 0.0f), (float)(WW - 1));
            int x0 = (int)floorf(xc);
            int x1i = min(x0 + 1, WW - 1);
            float lx = xc - (float)x0;
            float hx = 1.0f - lx;

            float v00 = __ldg(f + y0  * WW + x0);
            float v01 = __ldg(f + y0  * WW + x1i);
            float v10 = __ldg(f + y1i * WW + x0);
            float v11 = __ldg(f + y1i * WW + x1i);

            float v = v00 * (hy * hx) + v01 * (hy * lx)
                    + v10 * (ly * hx) + v11 * (ly * lx);

            acc += (ymask && xmask) ? v : 0.0f;
        }
    }

    out[tid] = acc * (1.0f / (SR * SR));
}

extern "C" void kernel_launch(void* const* d_in, const int* in_sizes, int n_in,
                              void* d_out, int out_size)
{
    const float* feat = (const float*)d_in[0];
    const float* rois = (const float*)d_in[1];
    float* out = (float*)d_out;

    int N = in_sizes[1] / 5;            // 512 rois
    int total = N * 16 * PH * PW;       // 401408 outputs

    int threads = 256;
    int blocks = (total + threads - 1) / threads;
    psroi_align_kernel<<<blocks, threads>>>(feat, rois, out, total);
}

// round 3
// speedup vs baseline: 1.1214x; 1.1214x over previous
#include <cuda_runtime.h>

// PSRoIAlign: feat [B=4, C=784, H=80, W=80] f32, rois [N=512, 5] f32
// out [N, 16, 7, 7] f32. Channel index of output element = r = co*49 + ph*7 + pw.
// SR=2 sampling, bilinear, mask outside [-1,H]/[-1,W], mean over 4 samples.
//
// R3: L1-wavefront reduction. Each sample's two x-taps (x0, x0+1) are covered
// by one aligned float4 load at xa = x0 & ~3 (valid unless x0%4==3, ~25% of
// cases -> predicated scalar fallback). 16 scalar LDGs -> 8 LDG.128 + ~2
// active fallbacks. All vector loads issued before consumption (high MLP).

#define PH 7
#define PW 7
#define HH 80
#define WW 80
#define CC 784
#define SR 2

__global__ void psroi_align_kernel(const float* __restrict__ feat,
                                   const float* __restrict__ rois,
                                   float* __restrict__ out,
                                   int total)
{
    int tid = blockIdx.x * blockDim.x + threadIdx.x;
    if (tid >= total) return;

    int n = tid / (PH * PW * 16);
    int r = tid - n * (PH * PW * 16);      // channel index
    int pw = r % PW;
    int ph = (r / PW) % PH;

    const float* roi = rois + n * 5;
    int   b  = (int)roi[0];
    float x1 = roi[1] * (float)WW;
    float y1 = roi[2] * (float)HH;
    float x2 = roi[3] * (float)WW;
    float y2 = roi[4] * (float)HH;

    float roi_h = fmaxf(y2 - y1, 0.1f);
    float roi_w = fmaxf(x2 - x1, 0.1f);
    float bin_h = roi_h * (1.0f / PH);
    float bin_w = roi_w * (1.0f / PW);

    const float* __restrict__ f = feat + ((size_t)b * CC + (size_t)r) * (HH * WW);

    // Per-sample state, fully unrolled -> registers.
    float4 qa[4], qb[4];          // row y0 / row y1i windows
    float  ea[4], eb[4];          // fallback taps when x0%4==3
    float  hy_[4], ly_[4], hx_[4], lx_[4], m_[4];
    int    o_[4];

    #pragma unroll
    for (int s = 0; s < 4; ++s) {
        int sy = s >> 1;
        int sx = s & 1;

        float ys = y1 + (float)ph * bin_h + ((float)sy + 0.5f) * bin_h * (1.0f / SR);
        float xs = x1 + (float)pw * bin_w + ((float)sx + 0.5f) * bin_w * (1.0f / SR);

        bool mask = (ys >= -1.0f) && (ys <= (float)HH) &&
                    (xs >= -1.0f) && (xs <= (float)WW);
        m_[s] = mask ? 1.0f : 0.0f;

        float yc = fminf(fmaxf(ys, 0.0f), (float)(HH - 1));
        float xc = fminf(fmaxf(xs, 0.0f), (float)(WW - 1));
        int y0  = (int)floorf(yc);
        int x0  = (int)floorf(xc);
        int y1i = min(y0 + 1, HH - 1);
        int x1i = min(x0 + 1, WW - 1);

        float ly = yc - (float)y0;
        float lx = xc - (float)x0;
        ly_[s] = ly;  hy_[s] = 1.0f - ly;
        lx_[s] = lx;  hx_[s] = 1.0f - lx;

        int xa = x0 & ~3;
        int o  = x0 - xa;
        o_[s] = o;

        const float4* pa = (const float4*)(f + y0  * WW + xa);
        const float4* pb = (const float4*)(f + y1i * WW + xa);
        qa[s] = __ldg(pa);
        qb[s] = __ldg(pb);
        // Fallback only when x0 lands on the last slot of the float4 window.
        ea[s] = (o == 3) ? __ldg(f + y0  * WW + x1i) : 0.0f;
        eb[s] = (o == 3) ? __ldg(f + y1i * WW + x1i) : 0.0f;
    }

    float acc = 0.0f;

    #pragma unroll
    for (int s = 0; s < 4; ++s) {
        int o = o_[s];
        float4 a = qa[s], bq = qb[s];

        float v00 = (o == 0) ? a.x : (o == 1) ? a.y : (o == 2) ? a.z : a.w;
        float v01 = (o == 0) ? a.y : (o == 1) ? a.z : (o == 2) ? a.w : ea[s];
        float v10 = (o == 0) ? bq.x : (o == 1) ? bq.y : (o == 2) ? bq.z : bq.w;
        float v11 = (o == 0) ? bq.y : (o == 1) ? bq.z : (o == 2) ? bq.w : eb[s];

        float top = v00 * hx_[s] + v01 * lx_[s];
        float bot = v10 * hx_[s] + v11 * lx_[s];
        float v   = top * hy_[s] + bot * ly_[s];
        acc += m_[s] * v;
    }

    out[tid] = acc * (1.0f / (SR * SR));
}

extern "C" void kernel_launch(void* const* d_in, const int* in_sizes, int n_in,
                              void* d_out, int out_size)
{
    const float* feat = (const float*)d_in[0];
    const float* rois = (const float*)d_in[1];
    float* out = (float*)d_out;

    int N = in_sizes[1] / 5;            // 512 rois
    int total = N * 16 * PH * PW;       // 401408 outputs

    int threads = 256;
    int blocks = (total + threads - 1) / threads;
    psroi_align_kernel<<<blocks, threads>>>(feat, rois, out, total);
}

// round 5
// speedup vs baseline: 1.4775x; 1.3175x over previous
#include <cuda_runtime.h>

// PSRoIAlign: feat [B=4, C=784, H=80, W=80] f32, rois [N=512, 5] f32
// out [N, 16, 7, 7] f32. Channel index of output element = r = co*49 + ph*7 + pw.
//
// R4: per sy, the two x-samples share rows y0/y1i, and all 4 x-taps fit in
// [x0a, x0a+3] (since x0b - x0a <= 2). One aligned float4 + one predicated
// overflow float4 per row covers everything -> ~6 LDG.128/thread, no scalar
// fallback. sy processed sequentially to halve live state; occupancy capped
// via __launch_bounds__(256, 5).

#define PH 7
#define PW 7
#define HH 80
#define WW 80
#define CC 784

__device__ __forceinline__ float pick4(float4 v, int o) {
    float a = (o & 1) ? v.y : v.x;
    float b = (o & 1) ? v.w : v.z;
    return (o & 2) ? b : a;
}
__device__ __forceinline__ float pick8(float4 lo, float4 hi, int o) {
    float a = pick4(lo, o);
    float b = pick4(hi, o);       // uses o&1, o&2 only
    return (o & 4) ? b : a;
}

__global__ void __launch_bounds__(256, 5)
psroi_align_kernel(const float* __restrict__ feat,
                   const float* __restrict__ rois,
                   float* __restrict__ out,
                   int total)
{
    int tid = blockIdx.x * blockDim.x + threadIdx.x;
    if (tid >= total) return;

    int n = tid / (PH * PW * 16);
    int r = tid - n * (PH * PW * 16);      // channel index
    int pw = r % PW;
    int ph = (r / PW) % PH;

    const float* roi = rois + n * 5;
    int   b  = (int)roi[0];
    float rx1 = roi[1] * (float)WW;
    float ry1 = roi[2] * (float)HH;
    float rx2 = roi[3] * (float)WW;
    float ry2 = roi[4] * (float)HH;

    float roi_h = fmaxf(ry2 - ry1, 0.1f);
    float roi_w = fmaxf(rx2 - rx1, 0.1f);
    float bin_h = roi_h * (1.0f / PH);
    float bin_w = roi_w * (1.0f / PW);

    const float* __restrict__ f = feat + ((size_t)b * CC + (size_t)r) * (HH * WW);

    // x geometry is identical for both sy iterations: compute once.
    float xs0 = rx1 + (float)pw * bin_w + 0.25f * bin_w;
    float xs1 = rx1 + (float)pw * bin_w + 0.75f * bin_w;
    float mx0 = (xs0 >= -1.0f && xs0 <= (float)WW) ? 1.0f : 0.0f;
    float mx1 = (xs1 >= -1.0f && xs1 <= (float)WW) ? 1.0f : 0.0f;
    float xc0 = fminf(fmaxf(xs0, 0.0f), (float)(WW - 1));
    float xc1 = fminf(fmaxf(xs1, 0.0f), (float)(WW - 1));
    int x00 = (int)floorf(xc0);            // sample0 left tap
    int x01 = (int)floorf(xc1);            // sample1 left tap
    int x10 = min(x00 + 1, WW - 1);        // sample0 right tap
    int x11 = min(x01 + 1, WW - 1);        // sample1 right tap
    float lx0 = xc0 - (float)x00, hx0 = 1.0f - lx0;
    float lx1 = xc1 - (float)x01, hx1 = 1.0f - lx1;

    int xa = x00 & ~3;
    bool need_hi = (x11 - xa) > 3;         // implies xa <= 72 -> hi window in-bounds
    int o00 = x00 - xa;                    // 0..3
    int o01 = x10 - xa;                    // 0..4
    int o10 = x01 - xa;                    // 0..5
    int o11 = x11 - xa;                    // 0..6

    float acc = 0.0f;

    #pragma unroll
    for (int sy = 0; sy < 2; ++sy) {
        float ys = ry1 + (float)ph * bin_h + ((float)sy * 0.5f + 0.25f) * bin_h;
        float my = (ys >= -1.0f && ys <= (float)HH) ? 1.0f : 0.0f;
        float yc = fminf(fmaxf(ys, 0.0f), (float)(HH - 1));
        int y0  = (int)floorf(yc);
        int y1i = min(y0 + 1, HH - 1);
        float ly = yc - (float)y0;
        float hy = 1.0f - ly;

        const float* rowA = f + y0  * WW + xa;
        const float* rowB = f + y1i * WW + xa;

        float4 Alo = __ldg((const float4*)rowA);
        float4 Blo = __ldg((const float4*)rowB);
        float4 Ahi = make_float4(0.f, 0.f, 0.f, 0.f);
        float4 Bhi = make_float4(0.f, 0.f, 0.f, 0.f);
        if (need_hi) {
            Ahi = __ldg((const float4*)(rowA + 4));
            Bhi = __ldg((const float4*)(rowB + 4));
        }

        // sample sx=0: taps at o00 (<=3) and o01 (<=4)
        float a00 = pick4(Alo, o00);
        float a01 = pick8(Alo, Ahi, o01);
        float b00 = pick4(Blo, o00);
        float b01 = pick8(Blo, Bhi, o01);
        float s0 = (a00 * hx0 + a01 * lx0) * hy + (b00 * hx0 + b01 * lx0) * ly;

        // sample sx=1: taps at o10 (<=5) and o11 (<=6)
        float a10 = pick8(Alo, Ahi, o10);
        float a11 = pick8(Alo, Ahi, o11);
        float b10 = pick8(Blo, Bhi, o10);
        float b11 = pick8(Blo, Bhi, o11);
        float s1 = (a10 * hx1 + a11 * lx1) * hy + (b10 * hx1 + b11 * lx1) * ly;

        acc += my * (mx0 * s0 + mx1 * s1);
    }

    out[tid] = acc * 0.25f;
}

extern "C" void kernel_launch(void* const* d_in, const int* in_sizes, int n_in,
                              void* d_out, int out_size)
{
    const float* feat = (const float*)d_in[0];
    const float* rois = (const float*)d_in[1];
    float* out = (float*)d_out;

    int N = in_sizes[1] / 5;            // 512 rois
    int total = N * 16 * PH * PW;       // 401408 outputs

    int threads = 256;
    int blocks = (total + threads - 1) / threads;
    psroi_align_kernel<<<blocks, threads>>>(feat, rois, out, total);
}